// round 11
// baseline (speedup 1.0000x reference)
#include <cuda_runtime.h>

#define N_RES 2048
#define BATCH 16
#define LMAXP 13
#define NTYPES 20
#define MAXROWS 28672
#define MAXATOMS 26624

// duplicated transposed weights: per (t,m,l), 64 v-values stored as
// (w0,w0,w1,w1,...,w63,w63) -> 128 floats; lane p loads float4 at 4*p.
#define WATM_T2_ELEMS (NTYPES * LMAXP * LMAXP * 128)   // 432640
#define WAMN_T2_ELEMS (NTYPES * LMAXP * 128)           // 33280

__constant__ int c_reslen[NTYPES] = {3, 4, 5, 5, 6, 6, 6, 7, 7, 7, 7, 7, 8, 8, 8, 9, 10, 10, 11, 13};

__device__ int g_starts[N_RES];
__device__ int g_a2r[MAXATOMS];                 // atom -> residue
__device__ int4 g_rowdesc[MAXROWS];             // {type, m(-1 amn), residue, start}
__device__ float g_WatmT[WATM_T2_ELEMS];
__device__ float g_WamnT[WAMN_T2_ELEMS];
__device__ float4 g_diff[BATCH * MAXATOMS];     // (dx,dy,dz,0)

// ---------------------------------------------------------------------------
// Kernel A: exclusive prefix-sum of residue lengths -> g_starts (1 block).
// ---------------------------------------------------------------------------
__global__ void scan_kernel(const int* __restrict__ seq) {
    int t = threadIdx.x;  // 0..1023
    int l0 = c_reslen[seq[2 * t]];
    int l1 = c_reslen[seq[2 * t + 1]];
    int a = l0 + l1;

    int v = a;
#pragma unroll
    for (int off = 1; off < 32; off <<= 1) {
        int n = __shfl_up_sync(0xFFFFFFFFu, v, off);
        if ((t & 31) >= off) v += n;
    }
    __shared__ int wsum[32];
    if ((t & 31) == 31) wsum[t >> 5] = v;
    __syncthreads();
    if (t < 32) {
        int s = wsum[t];
        int x = s;
#pragma unroll
        for (int off = 1; off < 32; off <<= 1) {
            int n = __shfl_up_sync(0xFFFFFFFFu, x, off);
            if (t >= off) x += n;
        }
        wsum[t] = x - s;
    }
    __syncthreads();

    int excl = wsum[t >> 5] + (v - a);
    g_starts[2 * t] = excl;
    g_starts[2 * t + 1] = excl + l0;
}

// ---------------------------------------------------------------------------
// Kernel B: fused row-descriptor fill + weight transpose/duplicate.
//   idx <  N_RES                      -> per-residue descriptor + a2r fill
//   idx in [N_RES, N_RES+WATM_T2)    -> WatmT entry
//   idx in [.., +WAMN_T2)            -> WamnT entry
// ---------------------------------------------------------------------------
__global__ void fill_transpose_kernel(const int* __restrict__ seq,
                                      const float* __restrict__ W_amn,
                                      const float* __restrict__ W_atm,
                                      int atoms) {
    int idx = blockIdx.x * blockDim.x + threadIdx.x;
    if (idx < N_RES) {
        int i = idx;
        int t = seq[i];
        int L = c_reslen[t];
        int start = g_starts[i];
        for (int l = 0; l < L; l++) {
            g_rowdesc[start + l] = make_int4(t, l, i, start);
            g_a2r[start + l] = i;
        }
        g_rowdesc[atoms + i] = make_int4(t, -1, i, start);
        return;
    }
    int j = idx - N_RES;
    if (j < WATM_T2_ELEMS) {
        int k = j & 127;
        int r = j >> 7;
        int l = r % LMAXP; r /= LMAXP;
        int m = r % LMAXP;
        int t = r / LMAXP;
        int v = 2 * (k >> 2) + ((k >> 1) & 1);
        g_WatmT[j] = W_atm[((size_t)(t * LMAXP + m) * 64 + v) * LMAXP + l];
        return;
    }
    int j2 = j - WATM_T2_ELEMS;
    if (j2 < WAMN_T2_ELEMS) {
        int k = j2 & 127;
        int r = j2 >> 7;
        int l = r % LMAXP;
        int t = r / LMAXP;
        int o = 2 * (k >> 2) + ((k >> 1) & 1);
        g_WamnT[j2] = W_amn[((size_t)t * 64 + o) * LMAXP + l];
    }
}

// ---------------------------------------------------------------------------
// Kernel C: precompute diffs into float4 scratch. One thread per (b, atom).
// ---------------------------------------------------------------------------
__global__ void diff_kernel(const float* __restrict__ pos_atm,
                            const float* __restrict__ pos_amn,
                            int atoms) {
    int idx = blockIdx.x * blockDim.x + threadIdx.x;
    if (idx >= BATCH * atoms) return;
    int b = idx / atoms;
    int a = idx - b * atoms;
    int ri = g_a2r[a];
    const float* pa = pos_atm + (size_t)idx * 3;
    const float* pm = pos_amn + ((size_t)b * N_RES + ri) * 3;
    g_diff[idx] = make_float4(pa[0] - pm[0], pa[1] - pm[1], pa[2] - pm[2], 0.f);
}

// ---------------------------------------------------------------------------
// f32x2 helpers
// ---------------------------------------------------------------------------
#define FMA2(acc, w, d) \
    asm("fma.rn.f32x2 %0, %1, %2, %0;" : "+l"(acc) : "l"(w), "l"(d))

__device__ __forceinline__ void unpack2(unsigned long long a, float& x, float& y) {
    asm("mov.b64 {%0, %1}, %2;" : "=f"(x), "=f"(y) : "l"(a));
}

// ---------------------------------------------------------------------------
// Per-row compute: one warp per row, lane owns v = 2*lane, 2*lane+1.
// Weights pre-duplicated: wv[l] = ((w0,w0),(w1,w1)) -> 1 LDG.128 per l.
// Per (l,batch): 4 x fma.rn.f32x2, zero packing.
// ---------------------------------------------------------------------------
template <int L>
__device__ __forceinline__ void row_compute(
    const float4* __restrict__ gd,    // g_diff + start
    int atoms,
    const float* __restrict__ wt,     // dup weight base + 4*lane
    float* __restrict__ obase,        // + 6*lane applied by caller
    size_t ostride)
{
    ulonglong2 wv[L];
#pragma unroll
    for (int l = 0; l < L; l++)
        wv[l] = *reinterpret_cast<const ulonglong2*>(wt + l * 128);

#pragma unroll 1
    for (int b = 0; b < BATCH; b++) {
        const ulonglong2* d = reinterpret_cast<const ulonglong2*>(gd + (size_t)b * atoms);
        unsigned long long a0 = 0ull, a1 = 0ull, a2 = 0ull, a3 = 0ull;
#pragma unroll
        for (int l = 0; l < L; l++) {
            ulonglong2 dd = d[l];                 // (dx,dy),(dz,0)
            FMA2(a0, wv[l].x, dd.x);              // (x0,y0)
            FMA2(a1, wv[l].x, dd.y);              // (z0, 0)
            FMA2(a2, wv[l].y, dd.x);              // (x1,y1)
            FMA2(a3, wv[l].y, dd.y);              // (z1, 0)
        }
        float* o = obase + (size_t)b * ostride;
        float z0, j0, x1, y1, z1, j1;
        unpack2(a1, z0, j0);
        unpack2(a2, x1, y1);
        unpack2(a3, z1, j1);
        *reinterpret_cast<unsigned long long*>(o) = a0;            // x0,y0
        reinterpret_cast<float2*>(o)[1] = make_float2(z0, x1);
        reinterpret_cast<float2*>(o)[2] = make_float2(y1, z1);
    }
}

// ---------------------------------------------------------------------------
// Kernel D: main. One warp per output row. No smem, no barriers.
// ---------------------------------------------------------------------------
__global__ void __launch_bounds__(256, 3) posmix_main(
    float* __restrict__ out_atm,
    float* __restrict__ out_amn,
    int atoms, int nrows)
{
    const int gtid = blockIdx.x * 256 + threadIdx.x;
    const int row = gtid >> 5;
    const int lane = gtid & 31;
    if (row >= nrows) return;

    const int4 dsc = g_rowdesc[row];
    const int t = dsc.x;
    const int m = dsc.y;
    const int ri = dsc.z;
    const int start = dsc.w;
    const int L = c_reslen[t];

    const float4* gd = g_diff + start;
    const float* wt;
    float* obase;
    size_t ostride;
    if (m >= 0) {
        wt = g_WatmT + (size_t)((t * LMAXP + m) * LMAXP) * 128 + 4 * lane;
        obase = out_atm + (size_t)row * 192 + 6 * lane;
        ostride = (size_t)atoms * 192;
    } else {
        wt = g_WamnT + (size_t)(t * LMAXP) * 128 + 4 * lane;
        obase = out_amn + (size_t)ri * 192 + 6 * lane;
        ostride = (size_t)N_RES * 192;
    }

    switch (L) {
        case 3:  row_compute<3 >(gd, atoms, wt, obase, ostride); break;
        case 4:  row_compute<4 >(gd, atoms, wt, obase, ostride); break;
        case 5:  row_compute<5 >(gd, atoms, wt, obase, ostride); break;
        case 6:  row_compute<6 >(gd, atoms, wt, obase, ostride); break;
        case 7:  row_compute<7 >(gd, atoms, wt, obase, ostride); break;
        case 8:  row_compute<8 >(gd, atoms, wt, obase, ostride); break;
        case 9:  row_compute<9 >(gd, atoms, wt, obase, ostride); break;
        case 10: row_compute<10>(gd, atoms, wt, obase, ostride); break;
        case 11: row_compute<11>(gd, atoms, wt, obase, ostride); break;
        case 13: row_compute<13>(gd, atoms, wt, obase, ostride); break;
        default: break;
    }
}

// ---------------------------------------------------------------------------
// Launch
// in: 0 pos_atm (B, atoms, 3) f32
//     1 pos_amn (B, 2048, 3) f32
//     2 W_amn   (20, 64, 13) f32
//     3 W_atm   (20, 13, 64, 13) f32
//     4 seq_types (2048,) i32
// out: [x_v_atm (B, atoms, 64, 3) | x_v_amn (B, 2048, 64, 3)] f32
// ---------------------------------------------------------------------------
extern "C" void kernel_launch(void* const* d_in, const int* in_sizes, int n_in,
                              void* d_out, int out_size)
{
    const float* pos_atm = (const float*)d_in[0];
    const float* pos_amn = (const float*)d_in[1];
    const float* W_amn   = (const float*)d_in[2];
    const float* W_atm   = (const float*)d_in[3];
    const int*   seq     = (const int*)d_in[4];

    const int atoms = in_sizes[0] / (BATCH * 3);
    const int nrows = atoms + N_RES;

    float* out_atm = (float*)d_out;
    float* out_amn = out_atm + (size_t)BATCH * atoms * 64 * 3;

    scan_kernel<<<1, 1024>>>(seq);

    int ftotal = N_RES + WATM_T2_ELEMS + WAMN_T2_ELEMS;
    fill_transpose_kernel<<<(ftotal + 255) / 256, 256>>>(seq, W_amn, W_atm, atoms);

    diff_kernel<<<(BATCH * atoms + 255) / 256, 256>>>(pos_atm, pos_amn, atoms);

    int grid = ((nrows * 32) + 255) / 256;
    posmix_main<<<grid, 256>>>(out_atm, out_amn, atoms, nrows);
}